// round 5
// baseline (speedup 1.0000x reference)
#include <cuda_runtime.h>
#include <cuda_fp16.h>

#define NU 8192
#define NI 4096
#define DE 64
#define US 64          // ELL stride, user rows (deg ~Poisson(20.5))
#define IS 96          // ELL stride, item rows (deg ~Poisson(41))
#define EPSF 1e-7f
#define OU (NU*192)
#define NBLK 592       // 148 SMs * 4 CTAs — co-resident via __launch_bounds__(256,4)
#define NTHR 256

// ---------------- device scratch (no allocations) ----------------
__device__ int g_ucnt[NU];
__device__ int g_icnt[NI];
__device__ int g_ucols[NU*US];     // ELL rows of H   (user -> items), padded w/ dummy NI
__device__ int g_icols[NI*IS];     // ELL rows of H^T (item -> users), padded w/ dummy NU

__device__ float g_g1[NI], g_hci[NU];
__device__ float g_dvu[NU], g_de1u[NI], g_de2u[NI];
__device__ float g_dvi[NI], g_de1i[NU], g_de2i[NU];

__device__ float g_Xu[NU*DE],  g_Xi[NI*DE];          // residual X, fp32
// gather-source buffers: fp16 (half2 = 2 cols), ONE extra zero row for ELL padding
__device__ __half2 h_Xsu[(NU+1)*32], h_Xsi[(NI+1)*32];   // dv ⊙ X
__device__ __half2 h_Y1u[(NI+1)*32], h_Y1i[(NU+1)*32];
__device__ __half2 h_An[(NU+1)*32],  h_Am[(NI+1)*32];
__device__ __half2 h_Bn[(NI+1)*32],  h_Bm[(NU+1)*32];

__device__ unsigned g_bar_count = 0;
__device__ volatile unsigned g_bar_gen = 0;

// software grid barrier; all NBLK blocks co-resident. gpu-scope fence flushes L1
// on both sides, so plain cached loads of mutable globals are safe across stages.
__device__ __forceinline__ void gsync() {
    __syncthreads();
    if (threadIdx.x == 0) {
        __threadfence();
        unsigned gen = g_bar_gen;
        if (atomicAdd(&g_bar_count, 1u) == gridDim.x - 1) {
            g_bar_count = 0;
            __threadfence();
            g_bar_gen = gen + 1;
        } else {
            while (g_bar_gen == gen) { }
        }
        __threadfence();
    }
    __syncthreads();
}

// ---- core gather: n8 multiple of 8; groups of 8 unconditional 4B loads ----
__device__ __forceinline__ void gather8h(float2& acc, const __half2* __restrict__ X2,
                                         int i0, int i1, int i2, int n8, int lane) {
    for (int seg = 0; seg < n8; seg += 8) {
        int rr = (seg < 32) ? i0 : ((seg < 64) ? i1 : i2);
        int t0 = seg & 31;
        int c[8];
        #pragma unroll
        for (int k = 0; k < 8; k++) c[k] = __shfl_sync(~0u, rr, t0 + k);
        __half2 v[8];
        #pragma unroll
        for (int k = 0; k < 8; k++) v[k] = X2[c[k]*32 + lane];
        #pragma unroll
        for (int k = 0; k < 8; k++) {
            float2 f = __half22float2(v[k]);
            acc.x += f.x; acc.y += f.y;
        }
    }
}

// ---------------- SpMM over two independent halves (warp per row) ----------------
struct Half {
    const int* cols; int stride; const int* cnt;
    const __half2* X; __half2* out;
    const float* rs;            // RSOUT -> store scale, INIT -> init coeff
    const __half2* init;
    int n;
};

template<bool RSOUT, bool INIT>
__device__ __forceinline__ void spmm_pair(const Half& A, const Half& B,
                                          int gw, int nwarp, int lane) {
    int ntot = A.n + B.n;
    for (int r = gw; r < ntot; r += nwarp) {
        const Half& J = (r < A.n) ? A : B;
        int row = (r < A.n) ? r : r - A.n;
        int st = J.stride;
        int n  = min(J.cnt[row], st);
        int n8 = (n + 7) & ~7;
        const int* cp = J.cols + row * st;
        int i0 = cp[lane];
        int i1 = cp[lane + 32];
        int i2 = (64 + lane < st) ? cp[lane + 64] : 0;
        float2 acc = make_float2(0.f, 0.f);
        if (INIT) {
            float r0 = J.rs[row];
            float2 v = __half22float2(J.init[row*32 + lane]);
            acc.x = r0 * v.x; acc.y = r0 * v.y;
        }
        gather8h(acc, J.X, i0, i1, i2, n8, lane);
        if (RSOUT) { float sc = J.rs[row]; acc.x *= sc; acc.y *= sc; }
        J.out[row*32 + lane] = __float22half2_rn(acc);
    }
}

// ---------------- final: Z=Hm*S ; M=dv*Z+X ; X'=M@w+b ; Xs'=dv*X' ----------------
struct FHalf {
    const int* cols; int stride; const int* cnt;
    const __half2* S; float* Xbuf; __half2* Xs; const float* dv;
    float* outp; int n;
};

__device__ __forceinline__ void final_pair(const FHalf& A, const FHalf& B,
                                           const float* w, const float* b,
                                           int gw, int nwarp, int lane) {
    int ntot = A.n + B.n;
    for (int r = gw; r < ntot; r += nwarp) {
        const FHalf& J = (r < A.n) ? A : B;
        int row = (r < A.n) ? r : r - A.n;
        int st = J.stride;
        int n  = min(J.cnt[row], st);
        int n8 = (n + 7) & ~7;
        const int* cp = J.cols + row * st;
        int i0 = cp[lane];
        int i1 = cp[lane + 32];
        int i2 = (64 + lane < st) ? cp[lane + 64] : 0;
        float2 acc = make_float2(0.f, 0.f);
        gather8h(acc, J.S, i0, i1, i2, n8, lane);
        float dvr = J.dv[row];
        float2 x0 = ((const float2*)J.Xbuf)[row*32 + lane];
        float2 m2 = make_float2(dvr*acc.x + x0.x, dvr*acc.y + x0.y);
        const float2* W2 = (const float2*)w;
        float2 o = __ldg((const float2*)b + lane);
        #pragma unroll
        for (int k = 0; k < 64; k++) {
            float mk = __shfl_sync(~0u, (k & 1) ? m2.y : m2.x, k >> 1);
            float2 wk = __ldg(&W2[k*32 + lane]);
            o.x += mk*wk.x; o.y += mk*wk.y;
        }
        ((float2*)J.Xbuf)[row*32 + lane] = o;
        J.Xs[row*32 + lane] = __float22half2_rn(make_float2(dvr*o.x, dvr*o.y));
        ((float2*)(J.outp + (size_t)row * 192))[lane] = o;
    }
}

// ---------------- the single persistent kernel ----------------
__global__ void __launch_bounds__(NTHR, 4) k_all(
    const uint4* __restrict__ H,
    const float* __restrict__ ue, const float* __restrict__ ie,
    const float* __restrict__ w0, const float* __restrict__ b0,
    const float* __restrict__ w1, const float* __restrict__ b1,
    float* __restrict__ out)
{
    const int tid  = blockIdx.x * NTHR + threadIdx.x;
    const int nthr = gridDim.x * NTHR;
    const int gw   = tid >> 5, nwarp = nthr >> 5, lane = threadIdx.x & 31;

    // ---- stage 0: zero counters + dummy rows, copy embeddings, level-0 output ----
    for (int i = tid; i < NU; i += nthr) g_ucnt[i] = 0;
    for (int i = tid; i < NI; i += nthr) g_icnt[i] = 0;
    if (tid < 32) {   // zero the dummy row of every gather-source buffer
        __half2 z = __float2half2_rn(0.f);
        h_Xsu[NU*32 + tid] = z; h_Y1i[NU*32 + tid] = z;
        h_An [NU*32 + tid] = z; h_Bm [NU*32 + tid] = z;
        h_Xsi[NI*32 + tid] = z; h_Y1u[NI*32 + tid] = z;
        h_Am [NI*32 + tid] = z; h_Bn [NI*32 + tid] = z;
    }
    for (int i = tid; i < NU*DE; i += nthr) {
        float v = ue[i]; g_Xu[i] = v;
        out[(i >> 6)*192 + (i & 63)] = v;
    }
    for (int i = tid; i < NI*DE; i += nthr) {
        float v = ie[i]; g_Xi[i] = v;
        out[OU + (i >> 6)*192 + (i & 63)] = v;
    }
    gsync();

    // ---- stage 1: scan dense H, high-MLP (8 unconditional LDG.128 / thread / step) ----
    {
        const int total = NU * (NI/4);
        for (int base = gw * 256; base < total; base += nwarp * 256) {
            uint4 v[8];
            #pragma unroll
            for (int k = 0; k < 8; k++)
                v[k] = __ldcs(H + base + lane + k*32);
            #pragma unroll
            for (int k = 0; k < 8; k++) {
                if (v[k].x | v[k].y | v[k].z | v[k].w) {
                    int idx = base + lane + k*32;
                    int u  = idx >> 10;
                    int c0 = (idx & 1023) << 2;
                    unsigned f[4] = {v[k].x, v[k].y, v[k].z, v[k].w};
                    #pragma unroll
                    for (int e = 0; e < 4; e++) {
                        if (f[e]) {
                            int c = c0 + e;
                            int p = atomicAdd(&g_ucnt[u], 1); if (p < US) g_ucols[u*US + p] = c;
                            int q = atomicAdd(&g_icnt[c], 1); if (q < IS) g_icols[c*IS + q] = u;
                        }
                    }
                }
            }
        }
    }
    gsync();

    // ---- stage 2: g1/hci + fill ELL pad slots with dummy indices ----
    for (int r = gw; r < NI + NU; r += nwarp) {
        float s = 0.f;
        if (r < NI) {
            int i = r, n = min(g_icnt[i], IS);
            int n8 = (n + 7) & ~7;
            int* cpw = g_icols + i*IS;
            if (n + lane < n8) cpw[n + lane] = NU;      // dummy -> zero row
            for (int t = lane; t < n; t += 32) s += (float)g_ucnt[cpw[t]];
            for (int o = 16; o; o >>= 1) s += __shfl_down_sync(~0u, s, o);
            if (!lane) g_g1[i] = s;
        } else {
            int u = r - NI, n = min(g_ucnt[u], US);
            int n8 = (n + 7) & ~7;
            int* cpw = g_ucols + u*US;
            if (n + lane < n8) cpw[n + lane] = NI;      // dummy -> zero row
            for (int t = lane; t < n; t += 32) s += (float)g_icnt[cpw[t]];
            for (int o = 16; o; o >>= 1) s += __shfl_down_sync(~0u, s, o);
            if (!lane) g_hci[u] = s;
        }
    }
    gsync();

    // ---- stage 3: norms (dv, de1^2, de2^2) + prescale Xs = dv ⊙ X (fp16) ----
    for (int r = gw; r < NU + NI; r += nwarp) {
        float s = 0.f;
        if (r < NU) {
            int u = r, n = min(g_ucnt[u], US);
            const int* cp = g_ucols + u*US;
            for (int t = lane; t < n; t += 32) s += g_g1[cp[t]];
            for (int o = 16; o; o >>= 1) s += __shfl_xor_sync(~0u, s, o);
            float ru = (float)g_ucnt[u];
            float dv = rsqrtf(ru + s + EPSF);
            if (!lane) {
                g_dvu[u]  = dv;
                g_de1i[u] = 1.0f / (ru + EPSF);
                g_de2i[u] = 1.0f / (s + EPSF);
            }
            float2 x = ((const float2*)g_Xu)[u*32 + lane];
            h_Xsu[u*32 + lane] = __float22half2_rn(make_float2(dv*x.x, dv*x.y));
        } else {
            int i = r - NU, n = min(g_icnt[i], IS);
            const int* cp = g_icols + i*IS;
            for (int t = lane; t < n; t += 32) s += g_hci[cp[t]];
            for (int o = 16; o; o >>= 1) s += __shfl_xor_sync(~0u, s, o);
            float ci = (float)g_icnt[i];
            float dv = rsqrtf(ci + s + EPSF);
            if (!lane) {
                g_dvi[i]  = dv;
                g_de1u[i] = 1.0f / (ci + EPSF);
                g_de2u[i] = 1.0f / (s + EPSF);
            }
            float2 x = ((const float2*)g_Xi)[i*32 + lane];
            h_Xsi[i*32 + lane] = __float22half2_rn(make_float2(dv*x.x, dv*x.y));
        }
    }
    gsync();

    // ---- two layers ----
    const float* wv[2] = { w0, w1 };
    const float* bv[2] = { b0, b1 };
    for (int l = 0; l < 2; l++) {
        Half a, b2;
        // S1: Y1 = Hm^T (dv ⊙ X)
        a  = { g_icols, IS, g_icnt, h_Xsu, h_Y1u, nullptr, nullptr, NI };
        b2 = { g_ucols, US, g_ucnt, h_Xsi, h_Y1i, nullptr, nullptr, NU };
        spmm_pair<false, false>(a, b2, gw, nwarp, lane);
        gsync();
        // S2: P = Hm Y1
        a  = { g_ucols, US, g_ucnt, h_Y1u, h_An, nullptr, nullptr, NU };
        b2 = { g_icols, IS, g_icnt, h_Y1i, h_Bn, nullptr, nullptr, NI };
        spmm_pair<false, false>(a, b2, gw, nwarp, lane);
        gsync();
        // S3: Y2 = de2^2 ⊙ (Hm^T P)
        a  = { g_icols, IS, g_icnt, h_An, h_Am, g_de2u, nullptr, NI };
        b2 = { g_ucols, US, g_ucnt, h_Bn, h_Bm, g_de2i, nullptr, NU };
        spmm_pair<true, false>(a, b2, gw, nwarp, lane);
        gsync();
        // S4: Q = Hm Y2
        a  = { g_ucols, US, g_ucnt, h_Am, h_An, nullptr, nullptr, NU };
        b2 = { g_icols, IS, g_icnt, h_Bm, h_Bn, nullptr, nullptr, NI };
        spmm_pair<false, false>(a, b2, gw, nwarp, lane);
        gsync();
        // S5: S = de1^2 ⊙ Y1 + Hm^T Q
        a  = { g_icols, IS, g_icnt, h_An, h_Am, g_de1u, h_Y1u, NI };
        b2 = { g_ucols, US, g_ucnt, h_Bn, h_Bm, g_de1i, h_Y1i, NU };
        spmm_pair<false, true>(a, b2, gw, nwarp, lane);
        gsync();
        // S6: M = dv ⊙ (Hm S) + X ; X' = M@w + b ; Xs' = dv ⊙ X' ; write out slice
        FHalf fa = { g_ucols, US, g_ucnt, h_Am, g_Xu, h_Xsu, g_dvu, out + 64*(l+1),      NU };
        FHalf fb = { g_icols, IS, g_icnt, h_Bm, g_Xi, h_Xsi, g_dvi, out + OU + 64*(l+1), NI };
        final_pair(fa, fb, wv[l], bv[l], gw, nwarp, lane);
        if (l == 0) gsync();
    }
}

// ---------------- host launch: ONE kernel, graph-capturable ----------------
extern "C" void kernel_launch(void* const* d_in, const int* in_sizes, int n_in,
                              void* d_out, int out_size) {
    const uint4* H  = (const uint4*)d_in[0];
    const float* ue = (const float*)d_in[1];
    const float* ie = (const float*)d_in[2];
    const float* w0 = (const float*)d_in[3];
    const float* b0 = (const float*)d_in[4];
    const float* w1 = (const float*)d_in[5];
    const float* b1 = (const float*)d_in[6];
    float* out = (float*)d_out;

    k_all<<<NBLK, NTHR>>>(H, ue, ie, w0, b0, w1, b1, out);
}

// round 6
// speedup vs baseline: 1.0584x; 1.0584x over previous
#include <cuda_runtime.h>

#define NU 8192
#define NI 4096
#define DE 64
#define US 64          // ELL stride, user rows (deg ~Poisson(20.5))
#define IS 96          // ELL stride, item rows (deg ~Poisson(41))
#define EPSF 1e-7f
#define OU (NU*192)
#define NBLK 592       // stage kernel: 148 SMs * 4 CTAs co-resident
#define NTHR 256
#define SCANBLK 2048   // scan kernel: no barrier, go wide

// ---------------- device scratch (no allocations) ----------------
__device__ int g_ucnt[NU];
__device__ int g_icnt[NI];
__device__ int g_ucols[NU*US];     // ELL rows of H   (user -> items), padded w/ dummy NI
__device__ int g_icols[NI*IS];     // ELL rows of H^T (item -> users), padded w/ dummy NU

__device__ float g_g1[NI], g_hci[NU];
__device__ float g_dvu[NU], g_de1u[NI], g_de2u[NI];
__device__ float g_dvi[NI], g_de1i[NU], g_de2i[NU];

__device__ float g_Xu[NU*DE],  g_Xi[NI*DE];
// gather-source buffers: fp32, ONE extra all-zero row (dummy target for ELL padding)
__device__ float g_Xsu[(NU+1)*DE], g_Xsi[(NI+1)*DE];   // dv ⊙ X
__device__ float g_Y1u[(NI+1)*DE], g_Y1i[(NU+1)*DE];
__device__ float g_An[(NU+1)*DE],  g_Am[(NI+1)*DE];
__device__ float g_Bn[(NI+1)*DE],  g_Bm[(NU+1)*DE];

__device__ unsigned g_bar_count = 0;
__device__ volatile unsigned g_bar_gen = 0;

// software grid barrier; all NBLK blocks of the stage kernel co-resident.
__device__ __forceinline__ void gsync() {
    __syncthreads();
    if (threadIdx.x == 0) {
        __threadfence();
        unsigned gen = g_bar_gen;
        if (atomicAdd(&g_bar_count, 1u) == gridDim.x - 1) {
            g_bar_count = 0;
            __threadfence();
            g_bar_gen = gen + 1;
        } else {
            while (g_bar_gen == gen) __nanosleep(32);
        }
        __threadfence();
    }
    __syncthreads();
}

// ---- core gather: n8 multiple of 8; 8 unconditional LDG.64 + packed f32x2 adds ----
__device__ __forceinline__ void gather8(float2& accf, const float2* __restrict__ X2,
                                        int i0, int i1, int i2, int n8, int lane) {
    unsigned long long acc;
    asm("mov.b64 %0, {%1, %2};" : "=l"(acc) : "f"(accf.x), "f"(accf.y));
    for (int seg = 0; seg < n8; seg += 8) {
        int rr = (seg < 32) ? i0 : ((seg < 64) ? i1 : i2);
        int t0 = seg & 31;
        int c[8];
        #pragma unroll
        for (int k = 0; k < 8; k++) c[k] = __shfl_sync(~0u, rr, t0 + k);
        unsigned long long v[8];
        #pragma unroll
        for (int k = 0; k < 8; k++)
            v[k] = *reinterpret_cast<const unsigned long long*>(&X2[c[k]*32 + lane]);
        #pragma unroll
        for (int k = 0; k < 8; k++)
            asm("add.rn.f32x2 %0, %0, %1;" : "+l"(acc) : "l"(v[k]));
    }
    asm("mov.b64 {%0, %1}, %2;" : "=f"(accf.x), "=f"(accf.y) : "l"(acc));
}

// ---------------- SpMM over two independent halves (warp per row) ----------------
struct Half {
    const int* cols; int stride; const int* cnt;
    const float* X; float* out;
    const float* rs;            // RSOUT -> store scale, INIT -> init coeff
    const float* init;
    int n;
};

template<bool RSOUT, bool INIT>
__device__ __forceinline__ void spmm_pair(const Half& A, const Half& B,
                                          int gw, int nwarp, int lane) {
    int ntot = A.n + B.n;
    for (int r = gw; r < ntot; r += nwarp) {
        const Half& J = (r < A.n) ? A : B;
        int row = (r < A.n) ? r : r - A.n;
        int st = J.stride;
        int n  = min(J.cnt[row], st);
        int n8 = (n + 7) & ~7;
        const int* cp = J.cols + row * st;
        int i0 = cp[lane];
        int i1 = cp[lane + 32];
        int i2 = (64 + lane < st) ? cp[lane + 64] : 0;
        float2 acc = make_float2(0.f, 0.f);
        if (INIT) {
            float r0 = J.rs[row];
            float2 v = ((const float2*)J.init)[row*32 + lane];
            acc.x = r0 * v.x; acc.y = r0 * v.y;
        }
        gather8(acc, (const float2*)J.X, i0, i1, i2, n8, lane);
        if (RSOUT) { float sc = J.rs[row]; acc.x *= sc; acc.y *= sc; }
        ((float2*)J.out)[row*32 + lane] = acc;
    }
}

// ---------------- final: Z=Hm*S ; M=dv*Z+X ; X'=M@w+b ; Xs'=dv*X' ----------------
struct FHalf {
    const int* cols; int stride; const int* cnt;
    const float* S; float* Xbuf; float* Xs; const float* dv;
    float* outp; int n;
};

__device__ __forceinline__ void final_pair(const FHalf& A, const FHalf& B,
                                           const float* w, const float* b,
                                           int gw, int nwarp, int lane) {
    int ntot = A.n + B.n;
    for (int r = gw; r < ntot; r += nwarp) {
        const FHalf& J = (r < A.n) ? A : B;
        int row = (r < A.n) ? r : r - A.n;
        int st = J.stride;
        int n  = min(J.cnt[row], st);
        int n8 = (n + 7) & ~7;
        const int* cp = J.cols + row * st;
        int i0 = cp[lane];
        int i1 = cp[lane + 32];
        int i2 = (64 + lane < st) ? cp[lane + 64] : 0;
        float2 acc = make_float2(0.f, 0.f);
        gather8(acc, (const float2*)J.S, i0, i1, i2, n8, lane);
        float dvr = J.dv[row];
        float2 x0 = ((const float2*)J.Xbuf)[row*32 + lane];
        float2 m2 = make_float2(dvr*acc.x + x0.x, dvr*acc.y + x0.y);
        const float2* W2 = (const float2*)w;
        float2 o = __ldg((const float2*)b + lane);
        #pragma unroll
        for (int k = 0; k < 64; k++) {
            float mk = __shfl_sync(~0u, (k & 1) ? m2.y : m2.x, k >> 1);
            float2 wk = __ldg(&W2[k*32 + lane]);
            o.x += mk*wk.x; o.y += mk*wk.y;
        }
        ((float2*)J.Xbuf)[row*32 + lane] = o;
        ((float2*)J.Xs)[row*32 + lane]   = make_float2(dvr*o.x, dvr*o.y);
        ((float2*)(J.outp + (size_t)row * 192))[lane] = o;
    }
}

// ============ kernel 1: zero counters, copy embeddings, level-0 output ============
__global__ void __launch_bounds__(NTHR) k_init(
    const float* __restrict__ ue, const float* __restrict__ ie,
    float* __restrict__ out)
{
    const int tid  = blockIdx.x * NTHR + threadIdx.x;
    const int nthr = gridDim.x * NTHR;
    for (int i = tid; i < NU; i += nthr) g_ucnt[i] = 0;
    for (int i = tid; i < NI; i += nthr) g_icnt[i] = 0;
    if (tid < DE) {   // zero the dummy row of every gather-source buffer
        g_Xsu[NU*DE + tid] = 0.f; g_Y1i[NU*DE + tid] = 0.f;
        g_An [NU*DE + tid] = 0.f; g_Bm [NU*DE + tid] = 0.f;
        g_Xsi[NI*DE + tid] = 0.f; g_Y1u[NI*DE + tid] = 0.f;
        g_Am [NI*DE + tid] = 0.f; g_Bn [NI*DE + tid] = 0.f;
    }
    for (int i = tid; i < NU*DE; i += nthr) {
        float v = ue[i]; g_Xu[i] = v;
        out[(i >> 6)*192 + (i & 63)] = v;
    }
    for (int i = tid; i < NI*DE; i += nthr) {
        float v = ie[i]; g_Xi[i] = v;
        out[OU + (i >> 6)*192 + (i & 63)] = v;
    }
}

// ============ kernel 2: dense H scan -> ELL CSR + CSC (wide grid) ============
__global__ void __launch_bounds__(NTHR) k_scan(const uint4* __restrict__ H)
{
    const int gw   = (blockIdx.x * NTHR + threadIdx.x) >> 5;
    const int nwarp = (gridDim.x * NTHR) >> 5;
    const int lane = threadIdx.x & 31;
    const int total = NU * (NI/4);
    for (int base = gw * 256; base < total; base += nwarp * 256) {
        uint4 v[8];
        #pragma unroll
        for (int k = 0; k < 8; k++)
            v[k] = __ldcs(H + base + lane + k*32);
        #pragma unroll
        for (int k = 0; k < 8; k++) {
            if (v[k].x | v[k].y | v[k].z | v[k].w) {
                int idx = base + lane + k*32;
                int u  = idx >> 10;
                int c0 = (idx & 1023) << 2;
                unsigned f[4] = {v[k].x, v[k].y, v[k].z, v[k].w};
                #pragma unroll
                for (int e = 0; e < 4; e++) {
                    if (f[e]) {
                        int c = c0 + e;
                        int p = atomicAdd(&g_ucnt[u], 1); if (p < US) g_ucols[u*US + p] = c;
                        int q = atomicAdd(&g_icnt[c], 1); if (q < IS) g_icols[c*IS + q] = u;
                    }
                }
            }
        }
    }
}

// ============ kernel 3: persistent stages (norms + 2 layers) ============
__global__ void __launch_bounds__(NTHR, 4) k_stages(
    const float* __restrict__ w0, const float* __restrict__ b0,
    const float* __restrict__ w1, const float* __restrict__ b1,
    float* __restrict__ out)
{
    const int tid  = blockIdx.x * NTHR + threadIdx.x;
    const int nthr = gridDim.x * NTHR;
    const int gw   = tid >> 5, nwarp = nthr >> 5, lane = threadIdx.x & 31;

    // ---- stage 2: g1/hci + fill ELL pad slots with dummy indices ----
    for (int r = gw; r < NI + NU; r += nwarp) {
        float s = 0.f;
        if (r < NI) {
            int i = r, n = min(g_icnt[i], IS);
            int n8 = (n + 7) & ~7;
            int* cpw = g_icols + i*IS;
            if (n + lane < n8) cpw[n + lane] = NU;      // dummy -> zero row
            for (int t = lane; t < n; t += 32) s += (float)g_ucnt[cpw[t]];
            for (int o = 16; o; o >>= 1) s += __shfl_down_sync(~0u, s, o);
            if (!lane) g_g1[i] = s;
        } else {
            int u = r - NI, n = min(g_ucnt[u], US);
            int n8 = (n + 7) & ~7;
            int* cpw = g_ucols + u*US;
            if (n + lane < n8) cpw[n + lane] = NI;      // dummy -> zero row
            for (int t = lane; t < n; t += 32) s += (float)g_icnt[cpw[t]];
            for (int o = 16; o; o >>= 1) s += __shfl_down_sync(~0u, s, o);
            if (!lane) g_hci[u] = s;
        }
    }
    gsync();

    // ---- stage 3: norms (dv, de1^2, de2^2) + prescale Xs = dv ⊙ X ----
    for (int r = gw; r < NU + NI; r += nwarp) {
        float s = 0.f;
        if (r < NU) {
            int u = r, n = min(g_ucnt[u], US);
            const int* cp = g_ucols + u*US;
            for (int t = lane; t < n; t += 32) s += g_g1[cp[t]];
            for (int o = 16; o; o >>= 1) s += __shfl_xor_sync(~0u, s, o);
            float ru = (float)g_ucnt[u];
            float dv = rsqrtf(ru + s + EPSF);
            if (!lane) {
                g_dvu[u]  = dv;
                g_de1i[u] = 1.0f / (ru + EPSF);
                g_de2i[u] = 1.0f / (s + EPSF);
            }
            float2 x = ((const float2*)g_Xu)[u*32 + lane];
            ((float2*)g_Xsu)[u*32 + lane] = make_float2(dv*x.x, dv*x.y);
        } else {
            int i = r - NU, n = min(g_icnt[i], IS);
            const int* cp = g_icols + i*IS;
            for (int t = lane; t < n; t += 32) s += g_hci[cp[t]];
            for (int o = 16; o; o >>= 1) s += __shfl_xor_sync(~0u, s, o);
            float ci = (float)g_icnt[i];
            float dv = rsqrtf(ci + s + EPSF);
            if (!lane) {
                g_dvi[i]  = dv;
                g_de1u[i] = 1.0f / (ci + EPSF);
                g_de2u[i] = 1.0f / (s + EPSF);
            }
            float2 x = ((const float2*)g_Xi)[i*32 + lane];
            ((float2*)g_Xsi)[i*32 + lane] = make_float2(dv*x.x, dv*x.y);
        }
    }
    gsync();

    // ---- two layers ----
    const float* wv[2] = { w0, w1 };
    const float* bv[2] = { b0, b1 };
    for (int l = 0; l < 2; l++) {
        Half a, b2;
        // S1: Y1 = Hm^T (dv ⊙ X)
        a  = { g_icols, IS, g_icnt, g_Xsu, g_Y1u, nullptr, nullptr, NI };
        b2 = { g_ucols, US, g_ucnt, g_Xsi, g_Y1i, nullptr, nullptr, NU };
        spmm_pair<false, false>(a, b2, gw, nwarp, lane);
        gsync();
        // S2: P = Hm Y1
        a  = { g_ucols, US, g_ucnt, g_Y1u, g_An, nullptr, nullptr, NU };
        b2 = { g_icols, IS, g_icnt, g_Y1i, g_Bn, nullptr, nullptr, NI };
        spmm_pair<false, false>(a, b2, gw, nwarp, lane);
        gsync();
        // S3: Y2 = de2^2 ⊙ (Hm^T P)
        a  = { g_icols, IS, g_icnt, g_An, g_Am, g_de2u, nullptr, NI };
        b2 = { g_ucols, US, g_ucnt, g_Bn, g_Bm, g_de2i, nullptr, NU };
        spmm_pair<true, false>(a, b2, gw, nwarp, lane);
        gsync();
        // S4: Q = Hm Y2
        a  = { g_ucols, US, g_ucnt, g_Am, g_An, nullptr, nullptr, NU };
        b2 = { g_icols, IS, g_icnt, g_Bm, g_Bn, nullptr, nullptr, NI };
        spmm_pair<false, false>(a, b2, gw, nwarp, lane);
        gsync();
        // S5: S = de1^2 ⊙ Y1 + Hm^T Q
        a  = { g_icols, IS, g_icnt, g_An, g_Am, g_de1u, g_Y1u, NI };
        b2 = { g_ucols, US, g_ucnt, g_Bn, g_Bm, g_de1i, g_Y1i, NU };
        spmm_pair<false, true>(a, b2, gw, nwarp, lane);
        gsync();
        // S6: M = dv ⊙ (Hm S) + X ; X' = M@w + b ; Xs' = dv ⊙ X' ; write out slice
        FHalf fa = { g_ucols, US, g_ucnt, g_Am, g_Xu, g_Xsu, g_dvu, out + 64*(l+1),      NU };
        FHalf fb = { g_icols, IS, g_icnt, g_Bm, g_Xi, g_Xsi, g_dvi, out + OU + 64*(l+1), NI };
        final_pair(fa, fb, wv[l], bv[l], gw, nwarp, lane);
        if (l == 0) gsync();
    }
}

// ---------------- host launch: 3 kernels, graph-capturable ----------------
extern "C" void kernel_launch(void* const* d_in, const int* in_sizes, int n_in,
                              void* d_out, int out_size) {
    const uint4* H  = (const uint4*)d_in[0];
    const float* ue = (const float*)d_in[1];
    const float* ie = (const float*)d_in[2];
    const float* w0 = (const float*)d_in[3];
    const float* b0 = (const float*)d_in[4];
    const float* w1 = (const float*)d_in[5];
    const float* b1 = (const float*)d_in[6];
    float* out = (float*)d_out;

    k_init  <<<NBLK, NTHR>>>(ue, ie, out);
    k_scan  <<<SCANBLK, NTHR>>>(H);
    k_stages<<<NBLK, NTHR>>>(w0, b0, w1, b1, out);
}